// round 17
// baseline (speedup 1.0000x reference)
#include <cuda_runtime.h>
#include <cuda_fp16.h>
#include <math.h>
#include <stdint.h>

typedef unsigned long long ull;

// Problem constants (fixed by the dataset)
#define B_DIM 16
#define N_DIM 8192
#define D_DIM 256
#define K_DIM 1024
#define R_TOTAL (B_DIM * N_DIM)     // 131072 rows

// GEMM tiling: 128x128 CTA tile, 8 warps of 64x32, K chunks of 64 fp16
#define BMT 128
#define BNT 128
#define NCHUNK 4                    // single-term fp16: K=256 = 4 chunks of 64
#define NSTAGE 3
#define A_STAGE 16384               // 128 rows * 128 B
#define B_STAGE 16384
#define STAGE_BYTES (A_STAGE + B_STAGE)
#define SMEM_DYN (NSTAGE * STAGE_BYTES)   // 98304 bytes -> 2 CTAs/SM

// Scratch (static device globals — no runtime allocation allowed)
__device__ __half g_xh[(size_t)R_TOTAL * D_DIM];
__device__ __half g_ch[(size_t)K_DIM * D_DIM];
__device__ __half g_e[(size_t)R_TOTAL * K_DIM];      // f = exp(shift - dist), fp16
__device__ float g_shift[(size_t)R_TOTAL * 32];      // per-(row, 32-col seg) shift
__device__ float g_x2[R_TOTAL];
__device__ float g_c2[K_DIM];
__device__ float g_row_partial[R_TOTAL];

// ---------------------------------------------------------------------------
// Helpers (sm_80 baseline; harness builds PTX at target sm_103 which rejects
// tcgen05/TMEM — mma.sync + cp.async path, verified rounds 6-14).
// ---------------------------------------------------------------------------
__device__ __forceinline__ uint32_t smem_u32(const void* p) {
    uint32_t a;
    asm("{ .reg .u64 t; cvta.to.shared.u64 t, %1; cvt.u32.u64 %0, t; }"
        : "=r"(a) : "l"(p));
    return a;
}
#define SWZ128(o) ((o) ^ (((o) >> 3) & 0x70))

__device__ __forceinline__ void cp_async16(uint32_t dst, const void* src) {
    asm volatile("cp.async.cg.shared.global [%0], [%1], 16;"
                 :: "r"(dst), "l"(src));
}
#define CP_COMMIT()  asm volatile("cp.async.commit_group;")
#define CP_WAIT_1()  asm volatile("cp.async.wait_group 1;")
#define CP_WAIT_0()  asm volatile("cp.async.wait_group 0;")

__device__ __forceinline__ void ldsm_x4(uint32_t& r0, uint32_t& r1,
                                        uint32_t& r2, uint32_t& r3,
                                        uint32_t addr) {
    asm volatile("ldmatrix.sync.aligned.m8n8.x4.shared.b16 {%0,%1,%2,%3}, [%4];"
                 : "=r"(r0), "=r"(r1), "=r"(r2), "=r"(r3) : "r"(addr));
}

__device__ __forceinline__ void mma_16816(float* c, const uint32_t* a,
                                          const uint32_t* b) {
    asm volatile(
        "mma.sync.aligned.m16n8k16.row.col.f32.f16.f16.f32 "
        "{%0,%1,%2,%3}, {%4,%5,%6,%7}, {%8,%9}, {%0,%1,%2,%3};"
        : "+f"(c[0]), "+f"(c[1]), "+f"(c[2]), "+f"(c[3])
        : "r"(a[0]), "r"(a[1]), "r"(a[2]), "r"(a[3]), "r"(b[0]), "r"(b[1]));
}

// ---------------------------------------------------------------------------
// Kernel 1: fp16 convert + fp32 squared norms. One warp per row.
// ---------------------------------------------------------------------------
__global__ __launch_bounds__(256) void prepack_kernel(const float* __restrict__ X,
                                                      const float* __restrict__ C) {
    const int warp_id = (blockIdx.x * blockDim.x + threadIdx.x) >> 5;
    const int lane = threadIdx.x & 31;
    if (warp_id >= R_TOTAL + K_DIM) return;

    const float* src;
    __half* dst;
    float* nrm;
    long r;
    if (warp_id < R_TOTAL) { src = X; dst = g_xh; nrm = g_x2; r = warp_id; }
    else { src = C; dst = g_ch; nrm = g_c2; r = warp_id - R_TOTAL; }

    const float4* p = reinterpret_cast<const float4*>(src + r * D_DIM);
    float4 va = p[lane * 2];
    float4 vb = p[lane * 2 + 1];
    float v[8] = {va.x, va.y, va.z, va.w, vb.x, vb.y, vb.z, vb.w};

    union { __half h[8]; uint4 u; } hv;
    float acc = 0.0f;
    #pragma unroll
    for (int i = 0; i < 8; i++) {
        acc = fmaf(v[i], v[i], acc);
        hv.h[i] = __float2half_rn(v[i]);
    }
    #pragma unroll
    for (int off = 16; off > 0; off >>= 1)
        acc += __shfl_xor_sync(0xFFFFFFFFu, acc, off);
    if (lane == 0) nrm[r] = acc;

    *reinterpret_cast<uint4*>(dst + r * D_DIM + lane * 8) = hv.u;
}

// ---------------------------------------------------------------------------
// Kernel 2: HMMA GEMM (fp16, K=256) -> epilogue stores f = exp(shift - dist)
// in fp16 (half the scratch bytes) + per-(row, 32-col-segment) shift.
// Shift = min dist over the warp's 32-col slice (2 quad shuffles, no smem).
// ---------------------------------------------------------------------------
__device__ __forceinline__ void load_stage(uint32_t a_s, uint32_t b_s,
                                           int rowBase, int colBase,
                                           int koff, int tid) {
    #pragma unroll
    for (int it = 0; it < 4; it++) {         // A tile: 128 rows x 8 x 16B
        int idx = it * 256 + tid;
        int row = idx >> 3, j = idx & 7;
        cp_async16(a_s + SWZ128(row * 128 + j * 16),
                   g_xh + (size_t)(rowBase + row) * D_DIM + koff + j * 8);
    }
    #pragma unroll
    for (int it = 0; it < 4; it++) {         // B tile: 128 rows x 8 x 16B
        int idx = it * 256 + tid;
        int row = idx >> 3, j = idx & 7;
        cp_async16(b_s + SWZ128(row * 128 + j * 16),
                   g_ch + (size_t)(colBase + row) * D_DIM + koff + j * 8);
    }
}

__global__ __launch_bounds__(256, 2) void sqdist_hmma_kernel() {
    extern __shared__ char smem[];
    const uint32_t sbase = smem_u32(smem);
    const int tid = threadIdx.x;
    const int wid = tid >> 5;
    const int lane = tid & 31;
    const int rowBase = blockIdx.y * BMT;
    const int colBase = blockIdx.x * BNT;
    const int warp_m = (wid >> 2) * 64;   // 0 or 64
    const int warp_n = (wid & 3) * 32;    // 0,32,64,96

    uint32_t a_s[NSTAGE], b_s[NSTAGE];
    #pragma unroll
    for (int s = 0; s < NSTAGE; s++) {
        a_s[s] = sbase + s * STAGE_BYTES;
        b_s[s] = a_s[s] + A_STAGE;
    }

    float acc[4][4][4];
    #pragma unroll
    for (int mt = 0; mt < 4; mt++)
        #pragma unroll
        for (int nt = 0; nt < 4; nt++)
            #pragma unroll
            for (int q = 0; q < 4; q++) acc[mt][nt][q] = 0.0f;

    #pragma unroll
    for (int c = 0; c < NSTAGE - 1; c++) {
        load_stage(a_s[c], b_s[c], rowBase, colBase, c * 64, tid);
        CP_COMMIT();
    }

    const uint32_t lrow = lane & 15;
    const uint32_t lkb = (lane >> 4) << 4;

    for (int c = 0; c < NCHUNK; c++) {
        CP_WAIT_1();
        __syncthreads();
        const int s = c % NSTAGE;
        if (c + NSTAGE - 1 < NCHUNK) {
            const int pf = c + NSTAGE - 1;
            load_stage(a_s[pf % NSTAGE], b_s[pf % NSTAGE], rowBase, colBase,
                       pf * 64, tid);
        }
        CP_COMMIT();

        const uint32_t a_cur = a_s[s], b_cur = b_s[s];
        #pragma unroll
        for (int ks = 0; ks < 4; ks++) {
            const uint32_t kb = ks * 32 + lkb;
            uint32_t af[4][4];
            #pragma unroll
            for (int mt = 0; mt < 4; mt++) {
                uint32_t row = warp_m + mt * 16 + lrow;
                ldsm_x4(af[mt][0], af[mt][1], af[mt][2], af[mt][3],
                        a_cur + SWZ128(row * 128 + kb));
            }
            uint32_t bf[4][2];
            #pragma unroll
            for (int nt2 = 0; nt2 < 2; nt2++) {
                uint32_t row = warp_n + nt2 * 16 + lrow;
                uint32_t m0, m1, m2, m3;
                ldsm_x4(m0, m1, m2, m3, b_cur + SWZ128(row * 128 + kb));
                bf[nt2 * 2 + 0][0] = m0; bf[nt2 * 2 + 0][1] = m2;
                bf[nt2 * 2 + 1][0] = m1; bf[nt2 * 2 + 1][1] = m3;
            }
            #pragma unroll
            for (int mt = 0; mt < 4; mt++)
                #pragma unroll
                for (int nt = 0; nt < 4; nt++)
                    mma_16816(acc[mt][nt], af[mt], bf[nt]);
        }
    }
    CP_WAIT_0();

    // ---- epilogue: dist -> per-seg shift -> f = exp(shift - dist) fp16 ----
    const int tgrp = lane >> 2;           // 0..7 (row within 8)
    const int tpair = (lane & 3) * 2;     // 0,2,4,6 (col pair)
    const int seg = (colBase + warp_n) >> 5;   // global 32-col segment index
    #pragma unroll
    for (int mt = 0; mt < 4; mt++) {
        const int m0 = rowBase + warp_m + mt * 16 + tgrp;
        const float x2a = __ldg(&g_x2[m0]);
        const float x2b = __ldg(&g_x2[m0 + 8]);
        float dminA = 1e30f, dminB = 1e30f;
        #pragma unroll
        for (int nt = 0; nt < 4; nt++) {
            const int n = colBase + warp_n + nt * 8 + tpair;
            const float c2a = __ldg(&g_c2[n]);
            const float c2b = __ldg(&g_c2[n + 1]);
            float d0 = sqrtf(fmaxf(x2a + c2a - 2.0f * acc[mt][nt][0], 0.0f));
            float d1 = sqrtf(fmaxf(x2a + c2b - 2.0f * acc[mt][nt][1], 0.0f));
            float d2 = sqrtf(fmaxf(x2b + c2a - 2.0f * acc[mt][nt][2], 0.0f));
            float d3 = sqrtf(fmaxf(x2b + c2b - 2.0f * acc[mt][nt][3], 0.0f));
            acc[mt][nt][0] = d0; acc[mt][nt][1] = d1;
            acc[mt][nt][2] = d2; acc[mt][nt][3] = d3;
            dminA = fminf(dminA, fminf(d0, d1));
            dminB = fminf(dminB, fminf(d2, d3));
        }
        // quad bfly-min: all 4 lanes (covering the 32-col slice) get the min
        dminA = fminf(dminA, __shfl_xor_sync(0xFFFFFFFFu, dminA, 1));
        dminA = fminf(dminA, __shfl_xor_sync(0xFFFFFFFFu, dminA, 2));
        dminB = fminf(dminB, __shfl_xor_sync(0xFFFFFFFFu, dminB, 1));
        dminB = fminf(dminB, __shfl_xor_sync(0xFFFFFFFFu, dminB, 2));
        if ((lane & 3) == 0) {
            g_shift[(size_t)m0 * 32 + seg] = dminA;
            g_shift[(size_t)(m0 + 8) * 32 + seg] = dminB;
        }
        #pragma unroll
        for (int nt = 0; nt < 4; nt++) {
            const int n = colBase + warp_n + nt * 8 + tpair;
            __half2 hA = __floats2half2_rn(__expf(dminA - acc[mt][nt][0]),
                                           __expf(dminA - acc[mt][nt][1]));
            __half2 hB = __floats2half2_rn(__expf(dminB - acc[mt][nt][2]),
                                           __expf(dminB - acc[mt][nt][3]));
            *reinterpret_cast<__half2*>(g_e + (size_t)m0 * K_DIM + n) = hA;
            *reinterpret_cast<__half2*>(g_e + (size_t)(m0 + 8) * K_DIM + n) = hB;
        }
    }
}

// ---------------------------------------------------------------------------
// Kernel 3: softmax from fp16 f + shifts. One block (256 thr) per row.
// e = f * exp(m* - m_seg);  dist = m_seg - ln f;  soft = e / sum(e).
// Reads 2KB fp16 + 128B shifts per row, writes 4KB fp32: 820MB total.
// ---------------------------------------------------------------------------
__global__ __launch_bounds__(256) void softmax_kernel(float* __restrict__ out) {
    __shared__ float sscale[32];   // exp(m* - m_seg)
    __shared__ float sshift[32];   // m_seg
    __shared__ float2 sbuf[8];
    const size_t row = blockIdx.x;
    const int tid = threadIdx.x;

    if (tid < 32) {
        float s = g_shift[row * 32 + tid];
        float m = s;
        #pragma unroll
        for (int off = 16; off > 0; off >>= 1)
            m = fminf(m, __shfl_xor_sync(0xFFFFFFFFu, m, off));
        sshift[tid] = s;
        sscale[tid] = __expf(m - s);   // <= 1
    }
    __syncthreads();

    // cols 4*tid .. 4*tid+3 (one 8-byte fp16 load)
    uint2 raw = reinterpret_cast<const uint2*>(g_e + row * K_DIM)[tid];
    const int seg = tid >> 3;
    const float sc = sscale[seg];
    const float ms = sshift[seg];
    __half2 p0 = *reinterpret_cast<__half2*>(&raw.x);
    __half2 p1 = *reinterpret_cast<__half2*>(&raw.y);
    float f0 = __low2float(p0), f1 = __high2float(p0);
    float f2 = __low2float(p1), f3 = __high2float(p1);

    float e0 = f0 * sc, e1 = f1 * sc, e2 = f2 * sc, e3 = f3 * sc;
    float d0 = ms - __logf(f0), d1 = ms - __logf(f1);
    float d2 = ms - __logf(f2), d3 = ms - __logf(f3);
    float sq0 = (f0 > 0.0f) ? d0 * d0 : 0.0f;
    float sq1 = (f1 > 0.0f) ? d1 * d1 : 0.0f;
    float sq2 = (f2 > 0.0f) ? d2 * d2 : 0.0f;
    float sq3 = (f3 > 0.0f) ? d3 * d3 : 0.0f;

    float2 v;
    v.x = e0 + e1 + e2 + e3;
    v.y = e0 * sq0 + e1 * sq1 + e2 * sq2 + e3 * sq3;

    #pragma unroll
    for (int off = 16; off > 0; off >>= 1) {
        v.x += __shfl_xor_sync(0xFFFFFFFFu, v.x, off);
        v.y += __shfl_xor_sync(0xFFFFFFFFu, v.y, off);
    }
    if ((tid & 31) == 0) sbuf[tid >> 5] = v;
    __syncthreads();
    if (tid < 32) {
        float2 w = (tid < 8) ? sbuf[tid] : make_float2(0.0f, 0.0f);
        #pragma unroll
        for (int off = 4; off > 0; off >>= 1) {
            w.x += __shfl_xor_sync(0xFFFFFFFFu, w.x, off);
            w.y += __shfl_xor_sync(0xFFFFFFFFu, w.y, off);
        }
        if (tid == 0) sbuf[0] = w;
    }
    __syncthreads();
    const float inv = 1.0f / sbuf[0].x;
    const float part = sbuf[0].y;

    float4 soft;
    soft.x = e0 * inv; soft.y = e1 * inv; soft.z = e2 * inv; soft.w = e3 * inv;
    reinterpret_cast<float4*>(out + row * K_DIM)[tid] = soft;

    if (tid == 0) g_row_partial[row] = part * inv;
}

// ---------------------------------------------------------------------------
// Kernel 4: deterministic reduction of row partials -> loss at out[last].
// ---------------------------------------------------------------------------
__global__ __launch_bounds__(1024) void loss_kernel(float* __restrict__ out,
                                                    long loss_idx) {
    __shared__ float s[1024];
    const int tid = threadIdx.x;
    float acc = 0.0f;
    for (int i = tid; i < R_TOTAL; i += 1024) acc += g_row_partial[i];
    s[tid] = acc;
    __syncthreads();
    #pragma unroll
    for (int stride = 512; stride > 0; stride >>= 1) {
        if (tid < stride) s[tid] += s[tid + stride];
        __syncthreads();
    }
    if (tid == 0) out[loss_idx] = s[0] / (float)B_DIM;
}

// ---------------------------------------------------------------------------
extern "C" void kernel_launch(void* const* d_in, const int* in_sizes, int n_in,
                              void* d_out, int out_size) {
    const float* X = (const float*)d_in[0];   // (16, 8192, 256) fp32
    const float* C = (const float*)d_in[1];   // (1024, 256) fp32
    float* out = (float*)d_out;               // soft (B,N,K) then loss scalar
    (void)in_sizes; (void)n_in;

    // 1) fp16 convert + norms
    {
        int total_warps = R_TOTAL + K_DIM;
        int blocks = (total_warps + 7) / 8;
        prepack_kernel<<<blocks, 256>>>(X, C);
    }
    // 2) GEMM -> fp16 shifted exponentials (half the scratch traffic)
    {
        cudaFuncSetAttribute(sqdist_hmma_kernel,
                             cudaFuncAttributeMaxDynamicSharedMemorySize,
                             SMEM_DYN);
        dim3 grid(K_DIM / BNT, R_TOTAL / BMT);   // (8, 1024)
        sqdist_hmma_kernel<<<grid, 256, SMEM_DYN>>>();
    }
    // 3) softmax from fp16 f + shifts -> fp32 soft + loss partials
    softmax_kernel<<<R_TOTAL, 256>>>(out);
    // 4) loss scalar
    {
        long loss_idx = (long)out_size - 1;
        loss_kernel<<<1, 1024>>>(out, loss_idx);
    }
}